// round 1
// baseline (speedup 1.0000x reference)
#include <cuda_runtime.h>

#define N_ROWS  65536
#define DIM     256
#define N_CODES 2048

#define TM 64
#define TN 64
#define KC 32
#define NTHREADS 256
// dynamic smem: sZ[DIM][TM] + sC[TN][KC+1]
#define SMEM_BYTES ((DIM*TM + TN*(KC+1)) * (int)sizeof(float))

// ---- device scratch (no allocations allowed) ----
__device__ float        g_cbsq[N_CODES];
__device__ int          g_best[N_ROWS];
__device__ unsigned int g_hist[N_CODES];
__device__ double       g_closs;

// ---- reset per-launch state (graph replays must be deterministic) ----
__global__ void zero_kernel() {
    int t = blockIdx.x * blockDim.x + threadIdx.x;
    if (t < N_CODES) g_hist[t] = 0u;
    if (t == 0) g_closs = 0.0;
}

// ---- ||w||^2 per code ----
__global__ void cbsq_kernel(const float* __restrict__ cb) {
    int code = blockIdx.x * 8 + (threadIdx.x >> 5);
    int lane = threadIdx.x & 31;
    const float4* r = (const float4*)(cb + (size_t)code * DIM);
    float s = 0.f;
#pragma unroll
    for (int j = 0; j < 2; j++) {
        float4 v = r[lane + 32 * j];
        s += v.x * v.x + v.y * v.y + v.z * v.z + v.w * v.w;
    }
#pragma unroll
    for (int off = 16; off; off >>= 1) s += __shfl_xor_sync(0xffffffffu, s, off);
    if (lane == 0) g_cbsq[code] = s;
}

// ---- fused distance GEMM + row argmin ----
// key(row, c) = ||w_c||^2 - 2 * <z_row, w_c>   (||z||^2 dropped: constant per row)
__global__ __launch_bounds__(NTHREADS) void argmin_kernel(
    const float* __restrict__ z, const float* __restrict__ cb) {
    extern __shared__ float smem[];
    float (*sZ)[TM]     = (float (*)[TM])smem;                 // transposed: sZ[k][m]
    float (*sC)[KC + 1] = (float (*)[KC + 1])(smem + DIM * TM); // sC[c][kk], padded

    const int tid = threadIdx.x;
    const int rowBase = blockIdx.x * TM;

    // load z tile (transposed). Coalesced global reads; one-time STS conflicts OK.
    for (int i = tid; i < TM * DIM; i += NTHREADS) {
        int m = i >> 8, k = i & 255;
        sZ[k][m] = z[(size_t)(rowBase + m) * DIM + k];
    }

    const int cg = tid & 15;  // code group: codes 4*cg .. 4*cg+3 (within tile)
    const int rg = tid >> 4;  // row  group: rows  4*rg .. 4*rg+3

    float bestKey[4] = {1e30f, 1e30f, 1e30f, 1e30f};
    int   bestIdx[4] = {0, 0, 0, 0};

    for (int ct = 0; ct < N_CODES; ct += TN) {
        float acc[4][4];
#pragma unroll
        for (int a = 0; a < 4; a++)
#pragma unroll
            for (int b = 0; b < 4; b++) acc[a][b] = 0.f;

        for (int kc = 0; kc < DIM; kc += KC) {
            __syncthreads();  // also covers initial sZ fill / previous-tile readers
            {   // load codebook chunk: conflict-free STS, coalesced LDG
                int c = tid >> 5, kk = tid & 31;
#pragma unroll
                for (int j = 0; j < 8; j++)
                    sC[c + 8 * j][kk] = cb[(size_t)(ct + c + 8 * j) * DIM + kc + kk];
            }
            __syncthreads();

#pragma unroll 8
            for (int k = 0; k < KC; k++) {
                float4 zv = *(const float4*)(&sZ[kc + k][rg * 4]);
                float c0 = sC[cg * 4 + 0][k];
                float c1 = sC[cg * 4 + 1][k];
                float c2 = sC[cg * 4 + 2][k];
                float c3 = sC[cg * 4 + 3][k];
                acc[0][0] += zv.x * c0; acc[0][1] += zv.x * c1; acc[0][2] += zv.x * c2; acc[0][3] += zv.x * c3;
                acc[1][0] += zv.y * c0; acc[1][1] += zv.y * c1; acc[1][2] += zv.y * c2; acc[1][3] += zv.y * c3;
                acc[2][0] += zv.z * c0; acc[2][1] += zv.z * c1; acc[2][2] += zv.z * c2; acc[2][3] += zv.z * c3;
                acc[3][0] += zv.w * c0; acc[3][1] += zv.w * c1; acc[3][2] += zv.w * c2; acc[3][3] += zv.w * c3;
            }
        }

        // fold tile into running best (ascending code order -> argmin ties pick first)
#pragma unroll
        for (int ci = 0; ci < 4; ci++) {
            int code = ct + cg * 4 + ci;
            float csq = g_cbsq[code];
#pragma unroll
            for (int ri = 0; ri < 4; ri++) {
                float key = csq - 2.f * acc[ri][ci];
                if (key < bestKey[ri]) { bestKey[ri] = key; bestIdx[ri] = code; }
            }
        }
    }

    // reduce across the 16 code-group lanes (xor <16 stays within half-warp)
#pragma unroll
    for (int ri = 0; ri < 4; ri++) {
        float k = bestKey[ri];
        int ix = bestIdx[ri];
#pragma unroll
        for (int off = 8; off; off >>= 1) {
            float k2 = __shfl_xor_sync(0xffffffffu, k, off);
            int   i2 = __shfl_xor_sync(0xffffffffu, ix, off);
            if (k2 < k || (k2 == k && i2 < ix)) { k = k2; ix = i2; }
        }
        if (cg == 0) g_best[rowBase + rg * 4 + ri] = ix;
    }
}

// ---- gather zq rows, exact commitment MSE partials, usage histogram ----
__global__ void gather_kernel(const float* __restrict__ z, const float* __restrict__ cb,
                              float* __restrict__ out_zq, float* __restrict__ out_idx,
                              int write_idx) {
    __shared__ float warp_s[8];
    int warp = threadIdx.x >> 5, lane = threadIdx.x & 31;
    int row = blockIdx.x * 8 + warp;
    int idx = g_best[row];

    const float4* src = (const float4*)(cb + (size_t)idx * DIM);
    const float4* zr  = (const float4*)(z + (size_t)row * DIM);
    float4*       dst = (float4*)(out_zq + (size_t)row * DIM);

    float s = 0.f;
#pragma unroll
    for (int j = 0; j < 2; j++) {
        int e = lane + 32 * j;
        float4 c = src[e];
        float4 v = zr[e];
        dst[e] = c;  // zq_st forward value == zq
        float dx = c.x - v.x, dy = c.y - v.y, dz = c.z - v.z, dw = c.w - v.w;
        s += dx * dx + dy * dy + dz * dz + dw * dw;
    }
#pragma unroll
    for (int off = 16; off; off >>= 1) s += __shfl_xor_sync(0xffffffffu, s, off);
    if (lane == 0) {
        warp_s[warp] = s;
        atomicAdd(&g_hist[idx], 1u);
        if (write_idx) out_idx[row] = (float)idx;
    }
    __syncthreads();
    if (threadIdx.x == 0) {
        float t = 0.f;
#pragma unroll
        for (int w = 0; w < 8; w++) t += warp_s[w];
        atomicAdd(&g_closs, (double)t);
    }
}

// ---- losses ----
__global__ void finalize_kernel(float* __restrict__ out_losses, int write_losses) {
    __shared__ double sh[256];
    int t = threadIdx.x;
    double e = 0.0;
    for (int c = t; c < N_CODES; c += 256) {
        float p = (float)g_hist[c] / (float)N_ROWS;
        e += (double)(p * logf(p + 1e-10f));
    }
    sh[t] = e;
    __syncthreads();
    for (int s = 128; s; s >>= 1) {
        if (t < s) sh[t] += sh[t + s];
        __syncthreads();
    }
    if (t == 0 && write_losses) {
        double entropy = -sh[0];
        float closs = (float)(g_closs / (double)((long long)N_ROWS * DIM));
        float maxent = logf((float)N_CODES);
        out_losses[0] = closs;
        out_losses[1] = maxent - (float)entropy;
    }
}

extern "C" void kernel_launch(void* const* d_in, const int* in_sizes, int n_in,
                              void* d_out, int out_size) {
    const float* z  = (const float*)d_in[0];
    const float* cb = (const float*)d_in[1];
    float* out = (float*)d_out;

    const long long ZQ = (long long)N_ROWS * DIM;  // 16,777,216
    int write_idx    = (long long)out_size >= ZQ + N_ROWS;
    int write_losses = (long long)out_size >= ZQ + N_ROWS + 2;

    cudaFuncSetAttribute(argmin_kernel,
                         cudaFuncAttributeMaxDynamicSharedMemorySize, SMEM_BYTES);

    zero_kernel<<<(N_CODES + 255) / 256, 256>>>();
    cbsq_kernel<<<N_CODES / 8, 256>>>(cb);
    argmin_kernel<<<N_ROWS / TM, NTHREADS, SMEM_BYTES>>>(z, cb);
    gather_kernel<<<N_ROWS / 8, 256>>>(z, cb, out, out + ZQ, write_idx);
    finalize_kernel<<<1, 256>>>(out + ZQ + N_ROWS, write_losses);
}